// round 10
// baseline (speedup 1.0000x reference)
#include <cuda_runtime.h>
#include <math.h>
#include <cstdint>

#define NB 64
#define NS 512
#define NF 1024
#define SST 36   // gemm smem row stride in floats (conflict-free fragments)

static __device__ float g_P[NB * NS * NF];      // x_proj, [b][s][h]
static __device__ float g_H[NB * NS * NF];      // x_rounded, then hidden states (tf32-rounded)
static __device__ float g_Wx[NF * NF];          // tf32-rounded W_x
static __device__ float g_Who[NF * NF];         // tf32-rounded W_ho
static __device__ float g_ring[2 * 1032 * 64];  // transposed h ring [slot][k][b]
static __device__ unsigned g_flag[2][64];       // per-(group,CTA) step progress flags

typedef unsigned long long ull;

__device__ __forceinline__ ull pack2(float x) {
    ull r; asm("mov.b64 %0, {%1, %1};" : "=l"(r) : "f"(x)); return r;
}
__device__ __forceinline__ float2 unpack2(ull v) {
    float2 r; asm("mov.b64 {%0, %1}, %2;" : "=f"(r.x), "=f"(r.y) : "l"(v)); return r;
}
__device__ __forceinline__ void fma2(ull& d, ull a, ull b) {
    asm("fma.rn.f32x2 %0, %1, %2, %0;" : "+l"(d) : "l"(a), "l"(b));
}
__device__ __forceinline__ float tf32r(float x) {
    float r; asm("cvt.rna.tf32.f32 %0, %1;" : "=f"(r) : "f"(x)); return r;
}
__device__ __forceinline__ uint32_t smem_u32(const void* p) {
    uint32_t a;
    asm("{ .reg .u64 t; cvta.to.shared.u64 t, %1; cvt.u32.u64 %0, t; }" : "=r"(a) : "l"(p));
    return a;
}
__device__ __forceinline__ void cp_async16(uint32_t dst, const void* src) {
    asm volatile("cp.async.cg.shared.global [%0], [%1], 16;" :: "r"(dst), "l"(src) : "memory");
}
__device__ __forceinline__ void mma_m16n8k8(float* c, const uint32_t* a,
                                            uint32_t b0, uint32_t b1) {
    asm volatile(
        "mma.sync.aligned.m16n8k8.row.col.f32.tf32.tf32.f32 "
        "{%0,%1,%2,%3}, {%4,%5,%6,%7}, {%8,%9}, {%0,%1,%2,%3};"
        : "+f"(c[0]), "+f"(c[1]), "+f"(c[2]), "+f"(c[3])
        : "r"(a[0]), "r"(a[1]), "r"(a[2]), "r"(a[3]), "r"(b0), "r"(b1));
}

__global__ void knop() {}

// ---------------------------------------------------------------------------
// Fused init: tf32-round x -> g_H, round weights, ring slot 1 <- h0^T, flags.
// ---------------------------------------------------------------------------
__global__ void fused_init(const float* __restrict__ x,
                           const float* __restrict__ Wih,
                           const float* __restrict__ Who,
                           const float* __restrict__ h0)
{
    int i = blockIdx.x * 256 + threadIdx.x;   // float4 idx
    float4 v = ((const float4*)x)[i];
    v.x = tf32r(v.x); v.y = tf32r(v.y); v.z = tf32r(v.z); v.w = tf32r(v.w);
    ((float4*)g_H)[i] = v;

    if (i < NF * NF) {
        int n = i >> 10, k = i & 1023;
        g_Wx[i]  = tf32r(Wih[(size_t)n * 2048 + k]);
        g_Who[i] = tf32r(Who[i]);
    }
    if (i < 65536) {
        int k = i >> 6, b = i & 63;
        g_ring[1032 * 64 + k * 64 + b] = h0[b * 1024 + k];
    }
    if (i < 128) ((unsigned*)g_flag)[i] = 0u;
}

// ---------------------------------------------------------------------------
// tf32 mma.sync GEMM v2 (measured ~600us; unchanged).
// ---------------------------------------------------------------------------
__global__ void __launch_bounds__(256, 1) gemm_mma(
    const float* __restrict__ A, const float* __restrict__ B,
    const float* __restrict__ bias, float* __restrict__ C)
{
    extern __shared__ float sm[];
    const int tid = threadIdx.x;
    const int wid = tid >> 5, lane = tid & 31;
    const int g = lane >> 2, tig = lane & 3;
    const int bm = blockIdx.y * 128, bn = blockIdx.x * 256;
    const int wm = (wid & 3) * 32;
    const int wn = (wid >> 2) * 128;

    const int ABUF = 128 * SST;
    const int BBUF = 256 * SST;
    const int STAGE = ABUF + BBUF;
    const uint32_t sbase = smem_u32(sm);

    const int arow = tid >> 1, ak = (tid & 1) * 16;
    const float* Ag = A + (size_t)(bm + arow) * 1024 + ak;
    const float* Bg = B + (size_t)(bn + tid) * 1024;
    const uint32_t dstA = sbase + (uint32_t)(arow * SST + ak) * 4;
    const uint32_t dstB = sbase + (uint32_t)(ABUF + tid * SST) * 4;

    float acc[2][16][4];
#pragma unroll
    for (int mt = 0; mt < 2; mt++)
#pragma unroll
        for (int nt = 0; nt < 16; nt++)
#pragma unroll
            for (int q = 0; q < 4; q++) acc[mt][nt][q] = 0.f;

    {
#pragma unroll
        for (int j = 0; j < 4; j++) cp_async16(dstA + j * 16, Ag + 4 * j);
#pragma unroll
        for (int j = 0; j < 8; j++) cp_async16(dstB + j * 16, Bg + 4 * j);
        asm volatile("cp.async.commit_group;" ::: "memory");
    }

    for (int c = 0; c < 32; ++c) {
        if (c + 1 < 32) {
            const uint32_t off = (uint32_t)(((c + 1) & 1) * STAGE) * 4;
            const float* ag = Ag + (c + 1) * 32;
            const float* bg = Bg + (c + 1) * 32;
#pragma unroll
            for (int j = 0; j < 4; j++) cp_async16(dstA + off + j * 16, ag + 4 * j);
#pragma unroll
            for (int j = 0; j < 8; j++) cp_async16(dstB + off + j * 16, bg + 4 * j);
            asm volatile("cp.async.commit_group;" ::: "memory");
            asm volatile("cp.async.wait_group 1;" ::: "memory");
        } else {
            asm volatile("cp.async.wait_group 0;" ::: "memory");
        }
        __syncthreads();

        const float* As_ = sm + (c & 1) * STAGE;
        const float* Bs_ = As_ + ABUF;
#pragma unroll
        for (int ks = 0; ks < 4; ks++) {
            const int k = ks * 8;
            uint32_t a[2][4];
#pragma unroll
            for (int mt = 0; mt < 2; mt++) {
                const float* ap = As_ + (wm + mt * 16 + g) * SST + k + tig;
                a[mt][0] = __float_as_uint(ap[0]);
                a[mt][1] = __float_as_uint(ap[8 * SST]);
                a[mt][2] = __float_as_uint(ap[4]);
                a[mt][3] = __float_as_uint(ap[8 * SST + 4]);
            }
#pragma unroll
            for (int nt = 0; nt < 16; nt++) {
                const float* bp = Bs_ + (wn + nt * 8 + g) * SST + k + tig;
                uint32_t b0 = __float_as_uint(bp[0]);
                uint32_t b1 = __float_as_uint(bp[4]);
                mma_m16n8k8(acc[0][nt], a[0], b0, b1);
                mma_m16n8k8(acc[1][nt], a[1], b0, b1);
            }
        }
        __syncthreads();
    }

#pragma unroll
    for (int mt = 0; mt < 2; mt++) {
        const size_t r0 = (size_t)(bm + wm + mt * 16 + g) * 1024;
#pragma unroll
        for (int nt = 0; nt < 16; nt++) {
            const int col = bn + wn + nt * 8 + 2 * tig;
            float2 bb = *(const float2*)&bias[col];
            float2 v0 = make_float2(acc[mt][nt][0] + bb.x, acc[mt][nt][1] + bb.y);
            float2 v1 = make_float2(acc[mt][nt][2] + bb.x, acc[mt][nt][3] + bb.y);
            *(float2*)&C[r0 + col] = v0;
            *(float2*)&C[r0 + 8 * 1024 + col] = v1;
        }
    }
}

// ---------------------------------------------------------------------------
// Persistent recurrence scan (round-7 core) + flag-array grid barrier.
// 128 CTAs x 512 threads, 2 batch-groups of 64 CTAs. CTA owns 16 n; W_h
// n-major in SMEM (64 KB; leaves L1 big enough for the 128 KB ring half).
// Barrier: CTA writes s+1 into its own flag (st.release, no atomic
// serialization); warps 14-15 (64 lanes) each spin on one flag while
// threads 0-255 overlap g_H writes + g_P prefetch.
// ---------------------------------------------------------------------------
__global__ void __launch_bounds__(512, 1) rnn_scan(const float* __restrict__ Wih)
{
    extern __shared__ float smf[];
    float* wsm = smf;                    // [1024 k][16 n] n-major (64 KB)
    ull* red = (ull*)(smf + 16384);      // [16 w][8 q][32 lane] (32 KB)

    const int tid  = threadIdx.x;
    const int warp = tid >> 5, lane = tid & 31;
    const int bq = lane & 7;             // 4-batch group within 32
    const int nq = lane >> 3;            // 4-n group within 16
    const int kbase = warp * 64;
    const int grp = blockIdx.x & 1;      // batch group
    const int cid = blockIdx.x >> 1;     // CTA id within group (0..63)
    const int NB0 = cid * 16;
    const int B0  = grp * 32;

    for (int idx = tid; idx < 16384; idx += 512) {
        int n = idx >> 10, k = idx & 1023;
        wsm[k * 16 + n] = Wih[(size_t)(NB0 + n) * 2048 + 1024 + k];
    }

    const int rq = tid >> 5, rl = tid & 31;            // valid for tid < 256
    const int rb = B0 + 4 * (rl & 7) + (rq >> 1);      // batch
    const int rn = NB0 + 4 * (rl >> 3) + 2 * (rq & 1); // even n
    const size_t pb = ((size_t)rb * NS) * NF + rn;

    __syncthreads();

    float2 pr = make_float2(0.f, 0.f);
    if (tid < 256) pr = *(const float2*)&g_P[pb];

    for (int s = 0; s < NS; ++s) {
        const float* __restrict__ hq =
            g_ring + ((s + 1) & 1) * (1032 * 64) + B0 + 4 * bq;

        ull acc[4][2];
#pragma unroll
        for (int i = 0; i < 4; i++) { acc[i][0] = 0ull; acc[i][1] = 0ull; }

        float4 pf[8];
#pragma unroll
        for (int j = 0; j < 8; ++j)
            pf[j] = *(const float4*)(hq + (kbase + j) * 64);
#pragma unroll 8
        for (int kk = 0; kk < 64; ++kk) {
            const int slot = kk & 7;
            float4 h = pf[slot];
            pf[slot] = *(const float4*)(hq + (kbase + kk + 8) * 64);
            ulonglong2 w = *(const ulonglong2*)(wsm + (kbase + kk) * 16 + 4 * nq);
            ull h0d = pack2(h.x), h1d = pack2(h.y);
            ull h2d = pack2(h.z), h3d = pack2(h.w);
            fma2(acc[0][0], h0d, w.x); fma2(acc[0][1], h0d, w.y);
            fma2(acc[1][0], h1d, w.x); fma2(acc[1][1], h1d, w.y);
            fma2(acc[2][0], h2d, w.x); fma2(acc[2][1], h2d, w.y);
            fma2(acc[3][0], h3d, w.x); fma2(acc[3][1], h3d, w.y);
        }

#pragma unroll
        for (int i = 0; i < 4; i++)
#pragma unroll
            for (int p = 0; p < 2; p++)
                red[((warp * 8) + (i * 2 + p)) * 32 + lane] = acc[i][p];
        __syncthreads();

        float r0 = 0.f, r1 = 0.f;
        if (tid < 256) {
            float sx = 0.f, sy = 0.f;
#pragma unroll
            for (int w2 = 0; w2 < 16; ++w2) {
                float2 v = unpack2(red[(w2 * 8 + rq) * 32 + rl]);
                sx += v.x; sy += v.y;
            }
            r0 = tanhf(sx + pr.x);
            r1 = tanhf(sy + pr.y);
            float* rc = g_ring + (s & 1) * (1032 * 64);
            rc[rn * 64 + rb] = r0;
            rc[(rn + 1) * 64 + rb] = r1;
        }

        if (s != NS - 1) {
            __syncthreads();                    // group ring rows complete
            if (tid == 256) {
                // Publish progress: own flag slot, no atomic contention.
                asm volatile("st.release.gpu.global.u32 [%0], %1;"
                             :: "l"(&g_flag[grp][cid]), "r"(s + 1) : "memory");
            }
            // Overlapped with the barrier: g_H writes + next g_P prefetch.
            if (tid < 256) {
                *(float2*)&g_H[pb + (size_t)s * NF] =
                    make_float2(tf32r(r0), tf32r(r1));
                pr = *(const float2*)&g_P[pb + (size_t)(s + 1) * NF];
            }
            // Warps 14-15: each lane spins on one CTA's flag (2 lines total).
            if (tid >= 448) {
                const unsigned tgt = (unsigned)(s + 1);
                unsigned v;
                do {
                    asm volatile("ld.acquire.gpu.global.u32 %0, [%1];"
                                 : "=r"(v) : "l"(&g_flag[grp][tid - 448]));
                } while (v < tgt);
            }
            __syncthreads();
        } else {
            if (tid < 256) {
                *(float2*)&g_H[pb + (size_t)s * NF] =
                    make_float2(tf32r(r0), tf32r(r1));
            }
        }
    }
}

extern "C" void kernel_launch(void* const* d_in, const int* in_sizes, int n_in,
                              void* d_out, int out_size)
{
    const float* x   = (const float*)d_in[0];
    const float* h0  = (const float*)d_in[1];
    const float* Wih = (const float*)d_in[2];
    const float* bih = (const float*)d_in[3];
    const float* Who = (const float*)d_in[4];
    const float* bho = (const float*)d_in[5];
    float* out = (float*)d_out;

    float *pP = nullptr, *pH = nullptr, *pWx = nullptr, *pWo = nullptr;
    cudaGetSymbolAddress((void**)&pP, g_P);
    cudaGetSymbolAddress((void**)&pH, g_H);
    cudaGetSymbolAddress((void**)&pWx, g_Wx);
    cudaGetSymbolAddress((void**)&pWo, g_Who);

    const int GEMM_SMEM = 2 * (128 + 256) * SST * 4;   // 110592 B
    const int SCAN_SMEM = 98304;

    static bool attr_done = false;
    if (!attr_done) {
        cudaFuncSetAttribute(rnn_scan, cudaFuncAttributeMaxDynamicSharedMemorySize, SCAN_SMEM);
        cudaFuncSetAttribute(gemm_mma, cudaFuncAttributeMaxDynamicSharedMemorySize, GEMM_SMEM);
        attr_done = true;
    }

    // user idx 0: fused init
    fused_init<<<32768, 256>>>(x, Wih, Who, h0);
    // user idx 1: x_proj = x_r @ W_x^T + b_ih -> g_P
    gemm_mma<<<dim3(4, 256), 256, GEMM_SMEM>>>(pH, pWx, bih, pP);
    // user idx 2: pad so profiler (user idx 3) hits the scan
    knop<<<1, 32>>>();
    // user idx 3: persistent recurrence scan  <-- ncu capture
    rnn_scan<<<128, 512, SCAN_SMEM>>>(Wih);
    // user idx 4: out = h_r @ W_ho^T + b_ho
    gemm_mma<<<dim3(4, 256), 256, GEMM_SMEM>>>(pH, pWo, bho, out);
}

// round 11
// speedup vs baseline: 1.1735x; 1.1735x over previous
#include <cuda_runtime.h>
#include <cuda_bf16.h>
#include <math.h>
#include <cstdint>

#define NB 64
#define NS 512
#define NF 1024
#define SST 36   // gemm smem row stride in floats
#define RS 64    // ring plane row stride (u32)
#define WS 17    // W plane smem row stride (u32)

static __device__ float g_P[NB * NS * NF];       // x_proj
static __device__ float g_H[NB * NS * NF];       // x_rounded, then tf32-rounded h
static __device__ float g_Wx[NF * NF];           // tf32-rounded W_x
static __device__ float g_Who[NF * NF];          // tf32-rounded W_ho
static __device__ uint32_t g_rp[2][2][512 * RS]; // h ring: [slot][hi/lo][k2*RS + b], bf16x2
static __device__ unsigned g_ctr[2 * NS];        // per-(step,group) arrival counters

__device__ __forceinline__ float tf32r(float x) {
    float r; asm("cvt.rna.tf32.f32 %0, %1;" : "=f"(r) : "f"(x)); return r;
}
__device__ __forceinline__ uint32_t smem_u32(const void* p) {
    uint32_t a;
    asm("{ .reg .u64 t; cvta.to.shared.u64 t, %1; cvt.u32.u64 %0, t; }" : "=r"(a) : "l"(p));
    return a;
}
__device__ __forceinline__ void cp_async16(uint32_t dst, const void* src) {
    asm volatile("cp.async.cg.shared.global [%0], [%1], 16;" :: "r"(dst), "l"(src) : "memory");
}
__device__ __forceinline__ void mma_m16n8k8(float* c, const uint32_t* a,
                                            uint32_t b0, uint32_t b1) {
    asm volatile(
        "mma.sync.aligned.m16n8k8.row.col.f32.tf32.tf32.f32 "
        "{%0,%1,%2,%3}, {%4,%5,%6,%7}, {%8,%9}, {%0,%1,%2,%3};"
        : "+f"(c[0]), "+f"(c[1]), "+f"(c[2]), "+f"(c[3])
        : "r"(a[0]), "r"(a[1]), "r"(a[2]), "r"(a[3]), "r"(b0), "r"(b1));
}
__device__ __forceinline__ void mma_bf16k16(float* c,
        uint32_t a0, uint32_t a1, uint32_t a2, uint32_t a3,
        uint32_t b0, uint32_t b1) {
    asm volatile(
        "mma.sync.aligned.m16n8k16.row.col.f32.bf16.bf16.f32 "
        "{%0,%1,%2,%3}, {%4,%5,%6,%7}, {%8,%9}, {%0,%1,%2,%3};"
        : "+f"(c[0]), "+f"(c[1]), "+f"(c[2]), "+f"(c[3])
        : "r"(a0), "r"(a1), "r"(a2), "r"(a3), "r"(b0), "r"(b1));
}
__device__ __forceinline__ uint32_t bfpack(__nv_bfloat16 a, __nv_bfloat16 b) {
    return (uint32_t)__bfloat16_as_ushort(a) | ((uint32_t)__bfloat16_as_ushort(b) << 16);
}

__global__ void knop() {}

// ---------------------------------------------------------------------------
// Fused init: tf32-round x -> g_H; round weights; ring slot 1 <- split(h0);
// zero counters.
// ---------------------------------------------------------------------------
__global__ void fused_init(const float* __restrict__ x,
                           const float* __restrict__ Wih,
                           const float* __restrict__ Who,
                           const float* __restrict__ h0)
{
    int i = blockIdx.x * 256 + threadIdx.x;   // float4 idx
    float4 v = ((const float4*)x)[i];
    v.x = tf32r(v.x); v.y = tf32r(v.y); v.z = tf32r(v.z); v.w = tf32r(v.w);
    ((float4*)g_H)[i] = v;

    if (i < NF * NF) {
        int n = i >> 10, k = i & 1023;
        g_Wx[i]  = tf32r(Wih[(size_t)n * 2048 + k]);
        g_Who[i] = tf32r(Who[i]);
    }
    if (i < 65536) {
        int k = i >> 6, b = i & 63;
        float hv = h0[b * 1024 + k];
        __nv_bfloat16 hi = __float2bfloat16(hv);
        __nv_bfloat16 lo = __float2bfloat16(hv - __bfloat162float(hi));
        unsigned short* phi = (unsigned short*)&g_rp[1][0][(k >> 1) * RS + b];
        unsigned short* plo = (unsigned short*)&g_rp[1][1][(k >> 1) * RS + b];
        phi[k & 1] = __bfloat16_as_ushort(hi);
        plo[k & 1] = __bfloat16_as_ushort(lo);
    }
    if (i < 2 * NS) g_ctr[i] = 0u;
}

// ---------------------------------------------------------------------------
// tf32 mma.sync GEMM (round-7 version, measured 603us).
// ---------------------------------------------------------------------------
__global__ void __launch_bounds__(256, 2) gemm_mma(
    const float* __restrict__ A, const float* __restrict__ B,
    const float* __restrict__ bias, float* __restrict__ C)
{
    extern __shared__ float sm[];
    const int tid = threadIdx.x;
    const int wid = tid >> 5, lane = tid & 31;
    const int g = lane >> 2, tig = lane & 3;
    const int bm = blockIdx.y * 128, bn = blockIdx.x * 128;
    const int mbase = (wid >> 1) * 32, nbase = (wid & 1) * 64;

    const int BUF = 128 * SST;
    const uint32_t sbase = smem_u32(sm);

    const int lrow = tid >> 1, lk = (tid & 1) * 16;
    const float* Ag = A + (size_t)(bm + lrow) * 1024 + lk;
    const float* Bg = B + (size_t)(bn + lrow) * 1024 + lk;
    const uint32_t dstA = sbase + (uint32_t)(lrow * SST + lk) * 4;
    const uint32_t dstB = dstA + (uint32_t)BUF * 4;

    float acc[2][8][4];
#pragma unroll
    for (int mt = 0; mt < 2; mt++)
#pragma unroll
        for (int nt = 0; nt < 8; nt++)
#pragma unroll
            for (int q = 0; q < 4; q++) acc[mt][nt][q] = 0.f;

    {
#pragma unroll
        for (int j = 0; j < 4; j++) {
            cp_async16(dstA + j * 16, Ag + 4 * j);
            cp_async16(dstB + j * 16, Bg + 4 * j);
        }
        asm volatile("cp.async.commit_group;" ::: "memory");
    }

    for (int c = 0; c < 32; ++c) {
        if (c + 1 < 32) {
            const int st = (c + 1) & 1;
            const float* ag = Ag + (c + 1) * 32;
            const float* bg = Bg + (c + 1) * 32;
            const uint32_t off = (uint32_t)(st * 2 * BUF) * 4;
#pragma unroll
            for (int j = 0; j < 4; j++) {
                cp_async16(dstA + off + j * 16, ag + 4 * j);
                cp_async16(dstB + off + j * 16, bg + 4 * j);
            }
            asm volatile("cp.async.commit_group;" ::: "memory");
            asm volatile("cp.async.wait_group 1;" ::: "memory");
        } else {
            asm volatile("cp.async.wait_group 0;" ::: "memory");
        }
        __syncthreads();

        const float* As_ = sm + (c & 1) * 2 * BUF;
        const float* Bs_ = As_ + BUF;
#pragma unroll
        for (int ks = 0; ks < 4; ks++) {
            const int k = ks * 8;
            uint32_t a[2][4];
#pragma unroll
            for (int mt = 0; mt < 2; mt++) {
                const float* ap = As_ + (mbase + mt * 16 + g) * SST + k + tig;
                a[mt][0] = __float_as_uint(ap[0]);
                a[mt][1] = __float_as_uint(ap[8 * SST]);
                a[mt][2] = __float_as_uint(ap[4]);
                a[mt][3] = __float_as_uint(ap[8 * SST + 4]);
            }
#pragma unroll
            for (int nt = 0; nt < 8; nt++) {
                const float* bp = Bs_ + (nbase + nt * 8 + g) * SST + k + tig;
                uint32_t b0 = __float_as_uint(bp[0]);
                uint32_t b1 = __float_as_uint(bp[4]);
                mma_m16n8k8(acc[0][nt], a[0], b0, b1);
                mma_m16n8k8(acc[1][nt], a[1], b0, b1);
            }
        }
        __syncthreads();
    }

#pragma unroll
    for (int mt = 0; mt < 2; mt++) {
        const size_t r0 = (size_t)(bm + mbase + mt * 16 + g) * 1024;
#pragma unroll
        for (int nt = 0; nt < 8; nt++) {
            const int col = bn + nbase + nt * 8 + 2 * tig;
            float2 bb = *(const float2*)&bias[col];
            float2 v0 = make_float2(acc[mt][nt][0] + bb.x, acc[mt][nt][1] + bb.y);
            float2 v1 = make_float2(acc[mt][nt][2] + bb.x, acc[mt][nt][3] + bb.y);
            *(float2*)&C[r0 + col] = v0;
            *(float2*)&C[r0 + 8 * 1024 + col] = v1;
        }
    }
}

// ---------------------------------------------------------------------------
// Tensor-core recurrence scan. 128 CTAs x 512 threads, 2 batch-groups of 64.
// CTA: 32 batches x 16 n x 1024 k per step via mma.m16n8k16 bf16 with
// hi/lo error compensation: D = h1*W1 + h1*W2 + h2*W1 (f32 accum).
// Warp wid: ks=wid>>2 (k quarter), mt=(wid>>1)&1 (16-batch half), nt=wid&1
// (8-n half). W planes packed bf16x2 k-pairs in SMEM ([k2][WS], 68 KB).
// Ring: two bf16x2 planes [k2][b] (A-fragment-native packing).
// Reduce: 4-way k partials via 8 KB SMEM. Barrier: round-7 counter scheme.
// ---------------------------------------------------------------------------
__global__ void __launch_bounds__(512, 1) rnn_scan(const float* __restrict__ Wih)
{
    extern __shared__ uint32_t smw[];
    uint32_t* w1s = smw;                       // [512][WS]
    uint32_t* w2s = smw + 512 * WS;
    float4*   red = (float4*)(smw + 2 * 512 * WS);  // [16 wid][32 lane]

    const int tid = threadIdx.x;
    const int wid = tid >> 5, lane = tid & 31;
    const int g = lane >> 2, tig = lane & 3;
    const int ks = wid >> 2, mt = (wid >> 1) & 1, nt = wid & 1;
    const int grp = blockIdx.x & 1;
    const int cid = blockIdx.x >> 1;
    const int NB0 = cid * 16, B0 = grp * 32;

    // One-time: split W_h slice into bf16 hi/lo planes, k-pair packed.
    for (int idx = tid; idx < 8192; idx += 512) {
        int n = idx >> 9, k2 = idx & 511;
        const float* wp = Wih + (size_t)(NB0 + n) * 2048 + 1024 + 2 * k2;
        float wa = wp[0], wb = wp[1];
        __nv_bfloat16 ha = __float2bfloat16(wa);
        __nv_bfloat16 hb = __float2bfloat16(wb);
        __nv_bfloat16 la = __float2bfloat16(wa - __bfloat162float(ha));
        __nv_bfloat16 lb = __float2bfloat16(wb - __bfloat162float(hb));
        w1s[k2 * WS + n] = bfpack(ha, hb);
        w2s[k2 * WS + n] = bfpack(la, lb);
    }

    // Reader decode (tid < 128): q = output tile, owns batches (bA, bA+8),
    // n-pair (n0, n0+1).
    const int q = tid >> 5, rl = tid & 31;
    const int gr = rl >> 2, tr = rl & 3;
    const int bA = B0 + (q >> 1) * 16 + gr;
    const int n0 = NB0 + (q & 1) * 8 + 2 * tr;
    const int n2w = ((NB0 + (q & 1) * 8) >> 1) + tr;     // ring row for n-pair
    const size_t pbA = ((size_t)bA * NS) * NF + n0;
    const size_t pbB = ((size_t)(bA + 8) * NS) * NF + n0;

    const uint32_t colA = (uint32_t)(B0 + mt * 16 + g);
    const uint32_t wof = (uint32_t)(nt * 8 + g);

    __syncthreads();

    float2 prA = make_float2(0.f, 0.f), prB = make_float2(0.f, 0.f);
    if (tid < 128) {
        prA = *(const float2*)&g_P[pbA];
        prB = *(const float2*)&g_P[pbB];
    }

    for (int s = 0; s < NS; ++s) {
        const uint32_t* __restrict__ Phi = g_rp[(s + 1) & 1][0];
        const uint32_t* __restrict__ Plo = g_rp[(s + 1) & 1][1];

        float acc[4] = {0.f, 0.f, 0.f, 0.f};
#pragma unroll 4
        for (int t = 0; t < 16; ++t) {
            const int r0 = (ks * 16 + t) * 8;
            const uint32_t* rh = Phi + (uint32_t)(r0 + tig) * RS + colA;
            const uint32_t* rr = Plo + (uint32_t)(r0 + tig) * RS + colA;
            uint32_t a0 = rh[0], a1 = rh[8];
            uint32_t a2 = rh[4 * RS], a3 = rh[4 * RS + 8];
            uint32_t l0 = rr[0], l1 = rr[8];
            uint32_t l2 = rr[4 * RS], l3 = rr[4 * RS + 8];
            uint32_t b0 = w1s[(r0 + tig) * WS + wof];
            uint32_t b1 = w1s[(r0 + tig + 4) * WS + wof];
            uint32_t c0 = w2s[(r0 + tig) * WS + wof];
            uint32_t c1 = w2s[(r0 + tig + 4) * WS + wof];
            mma_bf16k16(acc, a0, a1, a2, a3, b0, b1);   // h1*W1
            mma_bf16k16(acc, a0, a1, a2, a3, c0, c1);   // h1*W2
            mma_bf16k16(acc, l0, l1, l2, l3, b0, b1);   // h2*W1
        }

        red[wid * 32 + lane] = make_float4(acc[0], acc[1], acc[2], acc[3]);
        __syncthreads();

        float v0 = 0.f, v1 = 0.f, v2 = 0.f, v3 = 0.f;
        if (tid < 128) {
            float4 r = red[q * 32 + rl];
#pragma unroll
            for (int k2 = 1; k2 < 4; ++k2) {
                float4 tpart = red[(k2 * 4 + q) * 32 + rl];
                r.x += tpart.x; r.y += tpart.y; r.z += tpart.z; r.w += tpart.w;
            }
            v0 = tanhf(r.x + prA.x);   // (bA, n0)
            v1 = tanhf(r.y + prA.y);   // (bA, n0+1)
            v2 = tanhf(r.z + prB.x);   // (bA+8, n0)
            v3 = tanhf(r.w + prB.y);   // (bA+8, n0+1)

            // Ring write: hi/lo planes, k-pair packed u32 per batch.
            uint32_t* whi = g_rp[s & 1][0];
            uint32_t* wlo = g_rp[s & 1][1];
            __nv_bfloat16 h0b = __float2bfloat16(v0);
            __nv_bfloat16 h1b = __float2bfloat16(v1);
            __nv_bfloat16 h2b = __float2bfloat16(v2);
            __nv_bfloat16 h3b = __float2bfloat16(v3);
            whi[n2w * RS + bA]     = bfpack(h0b, h1b);
            whi[n2w * RS + bA + 8] = bfpack(h2b, h3b);
            wlo[n2w * RS + bA] = bfpack(
                __float2bfloat16(v0 - __bfloat162float(h0b)),
                __float2bfloat16(v1 - __bfloat162float(h1b)));
            wlo[n2w * RS + bA + 8] = bfpack(
                __float2bfloat16(v2 - __bfloat162float(h2b)),
                __float2bfloat16(v3 - __bfloat162float(h3b)));
        }

        if (s != NS - 1) {
            __syncthreads();                    // group ring writes complete
            if (tid == 0) {
                asm volatile("red.release.gpu.global.add.u32 [%0], %1;"
                             :: "l"(&g_ctr[s * 2 + grp]), "r"(1u) : "memory");
            }
            // Overlapped with barrier: g_H writes + next g_P prefetch.
            if (tid < 128) {
                *(float2*)&g_H[pbA + (size_t)s * NF] =
                    make_float2(tf32r(v0), tf32r(v1));
                *(float2*)&g_H[pbB + (size_t)s * NF] =
                    make_float2(tf32r(v2), tf32r(v3));
                prA = *(const float2*)&g_P[pbA + (size_t)(s + 1) * NF];
                prB = *(const float2*)&g_P[pbB + (size_t)(s + 1) * NF];
            }
            if (tid == 0) {
                unsigned v;
                do {
                    asm volatile("ld.acquire.gpu.global.u32 %0, [%1];"
                                 : "=r"(v) : "l"(&g_ctr[s * 2 + grp]));
                } while (v < 64u);
            }
            __syncthreads();
        } else {
            if (tid < 128) {
                *(float2*)&g_H[pbA + (size_t)s * NF] =
                    make_float2(tf32r(v0), tf32r(v1));
                *(float2*)&g_H[pbB + (size_t)s * NF] =
                    make_float2(tf32r(v2), tf32r(v3));
            }
        }
    }
}

extern "C" void kernel_launch(void* const* d_in, const int* in_sizes, int n_in,
                              void* d_out, int out_size)
{
    const float* x   = (const float*)d_in[0];
    const float* h0  = (const float*)d_in[1];
    const float* Wih = (const float*)d_in[2];
    const float* bih = (const float*)d_in[3];
    const float* Who = (const float*)d_in[4];
    const float* bho = (const float*)d_in[5];
    float* out = (float*)d_out;

    float *pP = nullptr, *pH = nullptr, *pWx = nullptr, *pWo = nullptr;
    cudaGetSymbolAddress((void**)&pP, g_P);
    cudaGetSymbolAddress((void**)&pH, g_H);
    cudaGetSymbolAddress((void**)&pWx, g_Wx);
    cudaGetSymbolAddress((void**)&pWo, g_Who);

    const int GEMM_SMEM = 4 * 128 * SST * 4;                    // 73728 B
    const int SCAN_SMEM = 2 * 512 * WS * 4 + 16 * 32 * 16;      // 77824 B

    static bool attr_done = false;
    if (!attr_done) {
        cudaFuncSetAttribute(rnn_scan, cudaFuncAttributeMaxDynamicSharedMemorySize, SCAN_SMEM);
        cudaFuncSetAttribute(gemm_mma, cudaFuncAttributeMaxDynamicSharedMemorySize, GEMM_SMEM);
        attr_done = true;
    }

    // user idx 0: fused init
    fused_init<<<32768, 256>>>(x, Wih, Who, h0);
    // user idx 1: x_proj = x_r @ W_x^T + b_ih -> g_P
    gemm_mma<<<dim3(8, 256), 256, GEMM_SMEM>>>(pH, pWx, bih, pP);
    // user idx 2: pad so profiler (user idx 3) hits the scan
    knop<<<1, 32>>>();
    // user idx 3: tensor-core recurrence scan  <-- ncu capture
    rnn_scan<<<128, 512, SCAN_SMEM>>>(Wih);
    // user idx 4: out = h_r @ W_ho^T + b_ho
    gemm_mma<<<dim3(8, 256), 256, GEMM_SMEM>>>(pH, pWo, bho, out);
}

// round 12
// speedup vs baseline: 1.2473x; 1.0629x over previous
#include <cuda_runtime.h>
#include <cuda_bf16.h>
#include <math.h>
#include <cstdint>

#define NB 64
#define NS 512
#define NF 1024
#define SST 36   // gemm smem row stride in floats

// h ring: [slot][plane hi/lo][ ((T*4+tig)*64 + batch)*2 + p ] u32 (bf16x2)
// where k2 = T*8 + tig + 4p indexes the k-pair (2*k2, 2*k2+1).
static __device__ float g_P[NB * NS * NF];        // x_proj
static __device__ float g_H[NB * NS * NF];        // x_rounded, then tf32-rounded h
static __device__ float g_Wx[NF * NF];            // tf32-rounded W_x
static __device__ float g_Who[NF * NF];           // tf32-rounded W_ho
static __device__ uint32_t g_rp[2][2][32768];     // 512 KB total
static __device__ unsigned g_ctr[2 * NS];         // per-(step,group) counters

__device__ __forceinline__ float tf32r(float x) {
    float r; asm("cvt.rna.tf32.f32 %0, %1;" : "=f"(r) : "f"(x)); return r;
}
__device__ __forceinline__ uint32_t smem_u32(const void* p) {
    uint32_t a;
    asm("{ .reg .u64 t; cvta.to.shared.u64 t, %1; cvt.u32.u64 %0, t; }" : "=r"(a) : "l"(p));
    return a;
}
__device__ __forceinline__ void cp_async16(uint32_t dst, const void* src) {
    asm volatile("cp.async.cg.shared.global [%0], [%1], 16;" :: "r"(dst), "l"(src) : "memory");
}
__device__ __forceinline__ void mma_m16n8k8(float* c, const uint32_t* a,
                                            uint32_t b0, uint32_t b1) {
    asm volatile(
        "mma.sync.aligned.m16n8k8.row.col.f32.tf32.tf32.f32 "
        "{%0,%1,%2,%3}, {%4,%5,%6,%7}, {%8,%9}, {%0,%1,%2,%3};"
        : "+f"(c[0]), "+f"(c[1]), "+f"(c[2]), "+f"(c[3])
        : "r"(a[0]), "r"(a[1]), "r"(a[2]), "r"(a[3]), "r"(b0), "r"(b1));
}
__device__ __forceinline__ void mma_bf16k16(float* c,
        uint32_t a0, uint32_t a1, uint32_t a2, uint32_t a3,
        uint32_t b0, uint32_t b1) {
    asm volatile(
        "mma.sync.aligned.m16n8k16.row.col.f32.bf16.bf16.f32 "
        "{%0,%1,%2,%3}, {%4,%5,%6,%7}, {%8,%9}, {%0,%1,%2,%3};"
        : "+f"(c[0]), "+f"(c[1]), "+f"(c[2]), "+f"(c[3])
        : "r"(a0), "r"(a1), "r"(a2), "r"(a3), "r"(b0), "r"(b1));
}
__device__ __forceinline__ uint32_t bfpack(__nv_bfloat16 a, __nv_bfloat16 b) {
    return (uint32_t)__bfloat16_as_ushort(a) | ((uint32_t)__bfloat16_as_ushort(b) << 16);
}

__global__ void knop() {}

// ---------------------------------------------------------------------------
// Fused init: tf32-round x -> g_H; round weights; ring slot 1 <- split(h0).
// ---------------------------------------------------------------------------
__global__ void fused_init(const float* __restrict__ x,
                           const float* __restrict__ Wih,
                           const float* __restrict__ Who,
                           const float* __restrict__ h0)
{
    int i = blockIdx.x * 256 + threadIdx.x;   // float4 idx
    float4 v = ((const float4*)x)[i];
    v.x = tf32r(v.x); v.y = tf32r(v.y); v.z = tf32r(v.z); v.w = tf32r(v.w);
    ((float4*)g_H)[i] = v;

    if (i < NF * NF) {
        int n = i >> 10, k = i & 1023;
        g_Wx[i]  = tf32r(Wih[(size_t)n * 2048 + k]);
        g_Who[i] = tf32r(Who[i]);
    }
    if (i < 65536) {
        int k = i >> 6, b = i & 63;
        int k2 = k >> 1, half = k & 1;
        int T = k2 >> 3, rem = k2 & 7, tg = rem & 3, p = rem >> 2;
        int idx = ((T * 4 + tg) * 64 + b) * 2 + p;
        float hv = h0[b * 1024 + k];
        __nv_bfloat16 hi = __float2bfloat16(hv);
        __nv_bfloat16 lo = __float2bfloat16(hv - __bfloat162float(hi));
        ((unsigned short*)&g_rp[1][0][idx])[half] = __bfloat16_as_ushort(hi);
        ((unsigned short*)&g_rp[1][1][idx])[half] = __bfloat16_as_ushort(lo);
    }
    if (i < 2 * NS) g_ctr[i] = 0u;
}

// ---------------------------------------------------------------------------
// tf32 mma.sync GEMM (round-7 version, measured 603us).
// ---------------------------------------------------------------------------
__global__ void __launch_bounds__(256, 2) gemm_mma(
    const float* __restrict__ A, const float* __restrict__ B,
    const float* __restrict__ bias, float* __restrict__ C)
{
    extern __shared__ float sm[];
    const int tid = threadIdx.x;
    const int wid = tid >> 5, lane = tid & 31;
    const int g = lane >> 2, tig = lane & 3;
    const int bm = blockIdx.y * 128, bn = blockIdx.x * 128;
    const int mbase = (wid >> 1) * 32, nbase = (wid & 1) * 64;

    const int BUF = 128 * SST;
    const uint32_t sbase = smem_u32(sm);

    const int lrow = tid >> 1, lk = (tid & 1) * 16;
    const float* Ag = A + (size_t)(bm + lrow) * 1024 + lk;
    const float* Bg = B + (size_t)(bn + lrow) * 1024 + lk;
    const uint32_t dstA = sbase + (uint32_t)(lrow * SST + lk) * 4;
    const uint32_t dstB = dstA + (uint32_t)BUF * 4;

    float acc[2][8][4];
#pragma unroll
    for (int mt = 0; mt < 2; mt++)
#pragma unroll
        for (int nt = 0; nt < 8; nt++)
#pragma unroll
            for (int q = 0; q < 4; q++) acc[mt][nt][q] = 0.f;

    {
#pragma unroll
        for (int j = 0; j < 4; j++) {
            cp_async16(dstA + j * 16, Ag + 4 * j);
            cp_async16(dstB + j * 16, Bg + 4 * j);
        }
        asm volatile("cp.async.commit_group;" ::: "memory");
    }

    for (int c = 0; c < 32; ++c) {
        if (c + 1 < 32) {
            const int st = (c + 1) & 1;
            const float* ag = Ag + (c + 1) * 32;
            const float* bg = Bg + (c + 1) * 32;
            const uint32_t off = (uint32_t)(st * 2 * BUF) * 4;
#pragma unroll
            for (int j = 0; j < 4; j++) {
                cp_async16(dstA + off + j * 16, ag + 4 * j);
                cp_async16(dstB + off + j * 16, bg + 4 * j);
            }
            asm volatile("cp.async.commit_group;" ::: "memory");
            asm volatile("cp.async.wait_group 1;" ::: "memory");
        } else {
            asm volatile("cp.async.wait_group 0;" ::: "memory");
        }
        __syncthreads();

        const float* As_ = sm + (c & 1) * 2 * BUF;
        const float* Bs_ = As_ + BUF;
#pragma unroll
        for (int ks = 0; ks < 4; ks++) {
            const int k = ks * 8;
            uint32_t a[2][4];
#pragma unroll
            for (int mt = 0; mt < 2; mt++) {
                const float* ap = As_ + (mbase + mt * 16 + g) * SST + k + tig;
                a[mt][0] = __float_as_uint(ap[0]);
                a[mt][1] = __float_as_uint(ap[8 * SST]);
                a[mt][2] = __float_as_uint(ap[4]);
                a[mt][3] = __float_as_uint(ap[8 * SST + 4]);
            }
#pragma unroll
            for (int nt = 0; nt < 8; nt++) {
                const float* bp = Bs_ + (nbase + nt * 8 + g) * SST + k + tig;
                uint32_t b0 = __float_as_uint(bp[0]);
                uint32_t b1 = __float_as_uint(bp[4]);
                mma_m16n8k8(acc[0][nt], a[0], b0, b1);
                mma_m16n8k8(acc[1][nt], a[1], b0, b1);
            }
        }
        __syncthreads();
    }

#pragma unroll
    for (int mt = 0; mt < 2; mt++) {
        const size_t r0 = (size_t)(bm + mbase + mt * 16 + g) * 1024;
#pragma unroll
        for (int nt = 0; nt < 8; nt++) {
            const int col = bn + nbase + nt * 8 + 2 * tig;
            float2 bb = *(const float2*)&bias[col];
            float2 v0 = make_float2(acc[mt][nt][0] + bb.x, acc[mt][nt][1] + bb.y);
            float2 v1 = make_float2(acc[mt][nt][2] + bb.x, acc[mt][nt][3] + bb.y);
            *(float2*)&C[r0 + col] = v0;
            *(float2*)&C[r0 + 8 * 1024 + col] = v1;
        }
    }
}

// ---------------------------------------------------------------------------
// Tensor-core recurrence scan v2. Same math as round 11 (D = h1W1 + h1W2 +
// h2W1, f32 accum), new memory system:
//  - ring re-keyed to the A fragment: (a0,a2)/(a1,a3) contiguous -> LDG.64
//  - W pre-baked fragment-major: one conflict-free LDS.128 per k16 tile
//  - explicit depth-4 software pipeline on ring loads
// ---------------------------------------------------------------------------
__global__ void __launch_bounds__(512, 1) rnn_scan(const float* __restrict__ Wih)
{
    extern __shared__ uint32_t smw[];
    uint4*  fragW = (uint4*)smw;                 // [2 nt][64 T][32 lane] 64 KB
    float4* red   = (float4*)(smw + 16384);      // [16 wid][32 lane] 8 KB

    const int tid = threadIdx.x;
    const int wid = tid >> 5, lane = tid & 31;
    const int g = lane >> 2, tig = lane & 3;
    const int ks = wid >> 2, mt = (wid >> 1) & 1, nt = wid & 1;
    const int grp = blockIdx.x & 1;
    const int cid = blockIdx.x >> 1;
    const int NB0 = cid * 16, B0 = grp * 32;

    // One-time: bake W_h slice into per-lane fragments (hi and lo planes).
    for (int e = tid; e < 4096; e += 512) {
        int nt_ = e >> 11, T_ = (e >> 5) & 63, l = e & 31;
        int tg = l & 3, gg = l >> 2;
        int n = NB0 + nt_ * 8 + gg;
        const float* wr = Wih + (size_t)n * 2048 + 1024;
        int ka = (T_ * 8 + tg) * 2, kb = ka + 8;
        float wa0 = wr[ka], wa1 = wr[ka + 1];
        float wb0 = wr[kb], wb1 = wr[kb + 1];
        __nv_bfloat16 ha0 = __float2bfloat16(wa0), ha1 = __float2bfloat16(wa1);
        __nv_bfloat16 hb0 = __float2bfloat16(wb0), hb1 = __float2bfloat16(wb1);
        uint4 u;
        u.x = bfpack(ha0, ha1);
        u.y = bfpack(hb0, hb1);
        u.z = bfpack(__float2bfloat16(wa0 - __bfloat162float(ha0)),
                     __float2bfloat16(wa1 - __bfloat162float(ha1)));
        u.w = bfpack(__float2bfloat16(wb0 - __bfloat162float(hb0)),
                     __float2bfloat16(wb1 - __bfloat162float(hb1)));
        fragW[(nt_ * 64 + T_) * 32 + l] = u;
    }

    // Writer decode (tid < 128): q = output tile; owns batches (bA, bA+8),
    // k-pair (n0, n0+1) of the next h.
    const int q = tid >> 5, rl = tid & 31;
    const int gr = rl >> 2, tr = rl & 3;
    const int bA = B0 + (q >> 1) * 16 + gr;
    const int n0 = NB0 + (q & 1) * 8 + 2 * tr;
    const int k2w = n0 >> 1;
    const int Tw = k2w >> 3, remw = k2w & 7;
    const int wbase = (((Tw * 4) + (remw & 3)) * 64 + bA) * 2 + (remw >> 2);
    const size_t pbA = ((size_t)bA * NS) * NF + n0;
    const size_t pbB = ((size_t)(bA + 8) * NS) * NF + n0;

    // Reader ring offsets (u32 units): row(T) = (T*4+tig)*128.
    const uint32_t cA2 = (uint32_t)(B0 + mt * 16 + g) * 2;
    const int Tbase = ks * 16;

    __syncthreads();

    float2 prA = make_float2(0.f, 0.f), prB = make_float2(0.f, 0.f);
    if (tid < 128) {
        prA = *(const float2*)&g_P[pbA];
        prB = *(const float2*)&g_P[pbB];
    }

    for (int s = 0; s < NS; ++s) {
        const uint32_t* __restrict__ Phi = g_rp[(s + 1) & 1][0];
        const uint32_t* __restrict__ Plo = g_rp[(s + 1) & 1][1];

        float acc[4] = {0.f, 0.f, 0.f, 0.f};

        // depth-4 pipelined k16 loop
        uint2 hA[4], hB[4], lA[4], lB[4];
#pragma unroll
        for (int j = 0; j < 4; ++j) {
            uint32_t ro = (uint32_t)((Tbase + j) * 4 + tig) * 128 + cA2;
            hA[j] = *(const uint2*)&Phi[ro];
            hB[j] = *(const uint2*)&Phi[ro + 16];
            lA[j] = *(const uint2*)&Plo[ro];
            lB[j] = *(const uint2*)&Plo[ro + 16];
        }
#pragma unroll
        for (int tt = 0; tt < 16; ++tt) {
            const int sl = tt & 3;
            uint2 a = hA[sl], b = hB[sl], c = lA[sl], d = lB[sl];
            if (tt < 12) {
                uint32_t ro = (uint32_t)((Tbase + tt + 4) * 4 + tig) * 128 + cA2;
                hA[sl] = *(const uint2*)&Phi[ro];
                hB[sl] = *(const uint2*)&Phi[ro + 16];
                lA[sl] = *(const uint2*)&Plo[ro];
                lB[sl] = *(const uint2*)&Plo[ro + 16];
            }
            uint4 w = fragW[(nt * 64 + Tbase + tt) * 32 + lane];
            mma_bf16k16(acc, a.x, b.x, a.y, b.y, w.x, w.y);   // h1*W1
            mma_bf16k16(acc, a.x, b.x, a.y, b.y, w.z, w.w);   // h1*W2
            mma_bf16k16(acc, c.x, d.x, c.y, d.y, w.x, w.y);   // h2*W1
        }

        red[wid * 32 + lane] = make_float4(acc[0], acc[1], acc[2], acc[3]);
        __syncthreads();

        float v0 = 0.f, v1 = 0.f, v2 = 0.f, v3 = 0.f;
        if (tid < 128) {
            float4 r = red[q * 32 + rl];
#pragma unroll
            for (int kq = 1; kq < 4; ++kq) {
                float4 t = red[(kq * 4 + q) * 32 + rl];
                r.x += t.x; r.y += t.y; r.z += t.z; r.w += t.w;
            }
            v0 = tanhf(r.x + prA.x);
            v1 = tanhf(r.y + prA.y);
            v2 = tanhf(r.z + prB.x);
            v3 = tanhf(r.w + prB.y);

            uint32_t* whi = g_rp[s & 1][0];
            uint32_t* wlo = g_rp[s & 1][1];
            __nv_bfloat16 h0b = __float2bfloat16(v0);
            __nv_bfloat16 h1b = __float2bfloat16(v1);
            __nv_bfloat16 h2b = __float2bfloat16(v2);
            __nv_bfloat16 h3b = __float2bfloat16(v3);
            whi[wbase]      = bfpack(h0b, h1b);
            whi[wbase + 16] = bfpack(h2b, h3b);
            wlo[wbase] = bfpack(
                __float2bfloat16(v0 - __bfloat162float(h0b)),
                __float2bfloat16(v1 - __bfloat162float(h1b)));
            wlo[wbase + 16] = bfpack(
                __float2bfloat16(v2 - __bfloat162float(h2b)),
                __float2bfloat16(v3 - __bfloat162float(h3b)));
        }

        if (s != NS - 1) {
            __syncthreads();                    // group ring writes complete
            if (tid == 0) {
                asm volatile("red.release.gpu.global.add.u32 [%0], %1;"
                             :: "l"(&g_ctr[s * 2 + grp]), "r"(1u) : "memory");
            }
            if (tid < 128) {
                *(float2*)&g_H[pbA + (size_t)s * NF] =
                    make_float2(tf32r(v0), tf32r(v1));
                *(float2*)&g_H[pbB + (size_t)s * NF] =
                    make_float2(tf32r(v2), tf32r(v3));
                prA = *(const float2*)&g_P[pbA + (size_t)(s + 1) * NF];
                prB = *(const float2*)&g_P[pbB + (size_t)(s + 1) * NF];
            }
            if (tid == 0) {
                unsigned v;
                do {
                    asm volatile("ld.acquire.gpu.global.u32 %0, [%1];"
                                 : "=r"(v) : "l"(&g_ctr[s * 2 + grp]));
                } while (v < 64u);
            }
            __syncthreads();
        } else {
            if (tid < 128) {
                *(float2*)&g_H[pbA + (size_t)s * NF] =
                    make_float2(tf32r(v0), tf32r(v1));
                *(float2*)&g_H[pbB + (size_t)s * NF] =
                    make_float2(tf32r(v2), tf32r(v3));
            }
        }
    }
}

extern "C" void kernel_launch(void* const* d_in, const int* in_sizes, int n_in,
                              void* d_out, int out_size)
{
    const float* x   = (const float*)d_in[0];
    const float* h0  = (const float*)d_in[1];
    const float* Wih = (const float*)d_in[2];
    const float* bih = (const float*)d_in[3];
    const float* Who = (const float*)d_in[4];
    const float* bho = (const float*)d_in[5];
    float* out = (float*)d_out;

    float *pP = nullptr, *pH = nullptr, *pWx = nullptr, *pWo = nullptr;
    cudaGetSymbolAddress((void**)&pP, g_P);
    cudaGetSymbolAddress((void**)&pH, g_H);
    cudaGetSymbolAddress((void**)&pWx, g_Wx);
    cudaGetSymbolAddress((void**)&pWo, g_Who);

    const int GEMM_SMEM = 4 * 128 * SST * 4;     // 73728 B
    const int SCAN_SMEM = 65536 + 8192;          // 73728 B

    static bool attr_done = false;
    if (!attr_done) {
        cudaFuncSetAttribute(rnn_scan, cudaFuncAttributeMaxDynamicSharedMemorySize, SCAN_SMEM);
        cudaFuncSetAttribute(gemm_mma, cudaFuncAttributeMaxDynamicSharedMemorySize, GEMM_SMEM);
        attr_done = true;
    }

    // user idx 0: fused init
    fused_init<<<32768, 256>>>(x, Wih, Who, h0);
    // user idx 1: x_proj = x_r @ W_x^T + b_ih -> g_P
    gemm_mma<<<dim3(8, 256), 256, GEMM_SMEM>>>(pH, pWx, bih, pP);
    // user idx 2: pad so profiler (user idx 3) hits the scan
    knop<<<1, 32>>>();
    // user idx 3: tensor-core recurrence scan  <-- ncu capture
    rnn_scan<<<128, 512, SCAN_SMEM>>>(Wih);
    // user idx 4: out = h_r @ W_ho^T + b_ho
    gemm_mma<<<dim3(8, 256), 256, GEMM_SMEM>>>(pH, pWo, bho, out);
}

// round 13
// speedup vs baseline: 1.4641x; 1.1738x over previous
#include <cuda_runtime.h>
#include <math.h>
#include <cstdint>

#define NB 64
#define NS 512
#define NF 1024
#define SST 36   // gemm smem row stride in floats

static __device__ float g_P[NB * NS * NF];      // x_proj, [b][s][h]
static __device__ float g_H[NB * NS * NF];      // x_rounded, then tf32-rounded h
static __device__ float g_Wx[NF * NF];          // tf32-rounded W_x
static __device__ float g_Who[NF * NF];         // tf32-rounded W_ho
static __device__ float g_ring[2 * 1032 * 64];  // transposed h ring [slot][k][b]
static __device__ unsigned g_qctr[2][4];        // per-(group, k-quarter) arrivals

typedef unsigned long long ull;

__device__ __forceinline__ ull pack2(float x) {
    ull r; asm("mov.b64 %0, {%1, %1};" : "=l"(r) : "f"(x)); return r;
}
__device__ __forceinline__ float2 unpack2(ull v) {
    float2 r; asm("mov.b64 {%0, %1}, %2;" : "=f"(r.x), "=f"(r.y) : "l"(v)); return r;
}
__device__ __forceinline__ void fma2(ull& d, ull a, ull b) {
    asm("fma.rn.f32x2 %0, %1, %2, %0;" : "+l"(d) : "l"(a), "l"(b));
}
__device__ __forceinline__ float tf32r(float x) {
    float r; asm("cvt.rna.tf32.f32 %0, %1;" : "=f"(r) : "f"(x)); return r;
}
__device__ __forceinline__ uint32_t smem_u32(const void* p) {
    uint32_t a;
    asm("{ .reg .u64 t; cvta.to.shared.u64 t, %1; cvt.u32.u64 %0, t; }" : "=r"(a) : "l"(p));
    return a;
}
__device__ __forceinline__ void cp_async16(uint32_t dst, const void* src) {
    asm volatile("cp.async.cg.shared.global [%0], [%1], 16;" :: "r"(dst), "l"(src) : "memory");
}
__device__ __forceinline__ void mma_m16n8k8(float* c, const uint32_t* a,
                                            uint32_t b0, uint32_t b1) {
    asm volatile(
        "mma.sync.aligned.m16n8k8.row.col.f32.tf32.tf32.f32 "
        "{%0,%1,%2,%3}, {%4,%5,%6,%7}, {%8,%9}, {%0,%1,%2,%3};"
        : "+f"(c[0]), "+f"(c[1]), "+f"(c[2]), "+f"(c[3])
        : "r"(a[0]), "r"(a[1]), "r"(a[2]), "r"(a[3]), "r"(b0), "r"(b1));
}

__global__ void knop() {}

// ---------------------------------------------------------------------------
// Fused init: tf32-round x -> g_H, round weights, ring slot 1 <- h0^T, ctrs.
// ---------------------------------------------------------------------------
__global__ void fused_init(const float* __restrict__ x,
                           const float* __restrict__ Wih,
                           const float* __restrict__ Who,
                           const float* __restrict__ h0)
{
    int i = blockIdx.x * 256 + threadIdx.x;   // float4 idx
    float4 v = ((const float4*)x)[i];
    v.x = tf32r(v.x); v.y = tf32r(v.y); v.z = tf32r(v.z); v.w = tf32r(v.w);
    ((float4*)g_H)[i] = v;

    if (i < NF * NF) {
        int n = i >> 10, k = i & 1023;
        g_Wx[i]  = tf32r(Wih[(size_t)n * 2048 + k]);
        g_Who[i] = tf32r(Who[i]);
    }
    if (i < 65536) {
        int k = i >> 6, b = i & 63;
        g_ring[1032 * 64 + k * 64 + b] = h0[b * 1024 + k];
    }
    if (i < 8) ((unsigned*)g_qctr)[i] = 0u;
}

// ---------------------------------------------------------------------------
// tf32 mma.sync GEMM (round-7 version, measured 603us; part of 4059us best).
// ---------------------------------------------------------------------------
__global__ void __launch_bounds__(256, 2) gemm_mma(
    const float* __restrict__ A, const float* __restrict__ B,
    const float* __restrict__ bias, float* __restrict__ C)
{
    extern __shared__ float sm[];
    const int tid = threadIdx.x;
    const int wid = tid >> 5, lane = tid & 31;
    const int g = lane >> 2, tig = lane & 3;
    const int bm = blockIdx.y * 128, bn = blockIdx.x * 128;
    const int mbase = (wid >> 1) * 32, nbase = (wid & 1) * 64;

    const int BUF = 128 * SST;
    const uint32_t sbase = smem_u32(sm);

    const int lrow = tid >> 1, lk = (tid & 1) * 16;
    const float* Ag = A + (size_t)(bm + lrow) * 1024 + lk;
    const float* Bg = B + (size_t)(bn + lrow) * 1024 + lk;
    const uint32_t dstA = sbase + (uint32_t)(lrow * SST + lk) * 4;
    const uint32_t dstB = dstA + (uint32_t)BUF * 4;

    float acc[2][8][4];
#pragma unroll
    for (int mt = 0; mt < 2; mt++)
#pragma unroll
        for (int nt = 0; nt < 8; nt++)
#pragma unroll
            for (int q = 0; q < 4; q++) acc[mt][nt][q] = 0.f;

    {
#pragma unroll
        for (int j = 0; j < 4; j++) {
            cp_async16(dstA + j * 16, Ag + 4 * j);
            cp_async16(dstB + j * 16, Bg + 4 * j);
        }
        asm volatile("cp.async.commit_group;" ::: "memory");
    }

    for (int c = 0; c < 32; ++c) {
        if (c + 1 < 32) {
            const int st = (c + 1) & 1;
            const float* ag = Ag + (c + 1) * 32;
            const float* bg = Bg + (c + 1) * 32;
            const uint32_t off = (uint32_t)(st * 2 * BUF) * 4;
#pragma unroll
            for (int j = 0; j < 4; j++) {
                cp_async16(dstA + off + j * 16, ag + 4 * j);
                cp_async16(dstB + off + j * 16, bg + 4 * j);
            }
            asm volatile("cp.async.commit_group;" ::: "memory");
            asm volatile("cp.async.wait_group 1;" ::: "memory");
        } else {
            asm volatile("cp.async.wait_group 0;" ::: "memory");
        }
        __syncthreads();

        const float* As_ = sm + (c & 1) * 2 * BUF;
        const float* Bs_ = As_ + BUF;
#pragma unroll
        for (int ks = 0; ks < 4; ks++) {
            const int k = ks * 8;
            uint32_t a[2][4];
#pragma unroll
            for (int mt = 0; mt < 2; mt++) {
                const float* ap = As_ + (mbase + mt * 16 + g) * SST + k + tig;
                a[mt][0] = __float_as_uint(ap[0]);
                a[mt][1] = __float_as_uint(ap[8 * SST]);
                a[mt][2] = __float_as_uint(ap[4]);
                a[mt][3] = __float_as_uint(ap[8 * SST + 4]);
            }
#pragma unroll
            for (int nt = 0; nt < 8; nt++) {
                const float* bp = Bs_ + (nbase + nt * 8 + g) * SST + k + tig;
                uint32_t b0 = __float_as_uint(bp[0]);
                uint32_t b1 = __float_as_uint(bp[4]);
                mma_m16n8k8(acc[0][nt], a[0], b0, b1);
                mma_m16n8k8(acc[1][nt], a[1], b0, b1);
            }
        }
        __syncthreads();
    }

#pragma unroll
    for (int mt = 0; mt < 2; mt++) {
        const size_t r0 = (size_t)(bm + mbase + mt * 16 + g) * 1024;
#pragma unroll
        for (int nt = 0; nt < 8; nt++) {
            const int col = bn + nbase + nt * 8 + 2 * tig;
            float2 bb = *(const float2*)&bias[col];
            float2 v0 = make_float2(acc[mt][nt][0] + bb.x, acc[mt][nt][1] + bb.y);
            float2 v1 = make_float2(acc[mt][nt][2] + bb.x, acc[mt][nt][3] + bb.y);
            *(float2*)&C[r0 + col] = v0;
            *(float2*)&C[r0 + 8 * 1024 + col] = v1;
        }
    }
}

// ---------------------------------------------------------------------------
// Persistent recurrence scan = round-7 core (proven 2.75 ms), with the global
// barrier replaced by producer-aligned QUARTER barriers:
//  - k-quarter Q (k in [256Q,256Q+256)) is produced by CTAs cid in
//    [16Q,16Q+16) of the same batch-group; each CTA release-adds 1 to
//    g_qctr[grp][cid>>4] per step (16-way arrival, not 64-way).
//  - warps of quarter Q gate on g_qctr[grp][Q] >= 16*s: warp 4Q polls
//    (acquire), warps 4Q..4Q+3 rendezvous on named barrier Q+1. Sleeping
//    warps issue nothing (avoids round-10 poll flood); ready quarters start
//    their k-loop without waiting for slow quarters or a CTA-wide wakeup.
// ---------------------------------------------------------------------------
__global__ void __launch_bounds__(512, 1) rnn_scan(const float* __restrict__ Wih)
{
    extern __shared__ float smf[];
    float* wsm = smf;                    // [1024 k][16 n] n-major (64 KB)
    ull* red = (ull*)(smf + 16384);      // [16 w][8 q][32 lane] (32 KB)

    const int tid  = threadIdx.x;
    const int warp = tid >> 5, lane = tid & 31;
    const int bq = lane & 7;             // 4-batch group within 32
    const int nq = lane >> 3;            // 4-n group within 16
    const int kbase = warp * 64;
    const int Q = warp >> 2;             // k-quarter this warp consumes
    const int grp = blockIdx.x & 1;      // batch group
    const int cid = blockIdx.x >> 1;     // CTA id within group (0..63)
    const int NB0 = cid * 16;
    const int B0  = grp * 32;
    unsigned* myctr = &g_qctr[grp][cid >> 4];   // counter this CTA produces
    unsigned* rdctr = &g_qctr[grp][Q];          // counter this warp consumes

    for (int idx = tid; idx < 16384; idx += 512) {
        int n = idx >> 10, k = idx & 1023;
        wsm[k * 16 + n] = Wih[(size_t)(NB0 + n) * 2048 + 1024 + k];
    }

    const int rq = tid >> 5, rl = tid & 31;            // valid for tid < 256
    const int rb = B0 + 4 * (rl & 7) + (rq >> 1);      // batch
    const int rn = NB0 + 4 * (rl >> 3) + 2 * (rq & 1); // even n
    const size_t pb = ((size_t)rb * NS) * NF + rn;

    __syncthreads();

    float2 pr = make_float2(0.f, 0.f);
    if (tid < 256) pr = *(const float2*)&g_P[pb];

    for (int s = 0; s < NS; ++s) {
        // Quarter gate: wait until the 16 producer CTAs of quarter Q have
        // finished step s-1. (Step 0 reads the pre-initialized slot 1.)
        if (s > 0) {
            if ((warp & 3) == 0) {
                const unsigned tgt = (unsigned)s << 4;
                unsigned v;
                do {
                    asm volatile("ld.acquire.gpu.global.u32 %0, [%1];"
                                 : "=r"(v) : "l"(rdctr));
                } while (v < tgt);
            }
            asm volatile("bar.sync %0, 128;" :: "r"(Q + 1) : "memory");
        }

        const float* __restrict__ hq =
            g_ring + ((s + 1) & 1) * (1032 * 64) + B0 + 4 * bq;

        ull acc[4][2];
#pragma unroll
        for (int i = 0; i < 4; i++) { acc[i][0] = 0ull; acc[i][1] = 0ull; }

        float4 pf[8];
#pragma unroll
        for (int j = 0; j < 8; ++j)
            pf[j] = *(const float4*)(hq + (kbase + j) * 64);
#pragma unroll 8
        for (int kk = 0; kk < 64; ++kk) {
            const int slot = kk & 7;
            float4 h = pf[slot];
            pf[slot] = *(const float4*)(hq + (kbase + kk + 8) * 64);
            ulonglong2 w = *(const ulonglong2*)(wsm + (kbase + kk) * 16 + 4 * nq);
            ull h0d = pack2(h.x), h1d = pack2(h.y);
            ull h2d = pack2(h.z), h3d = pack2(h.w);
            fma2(acc[0][0], h0d, w.x); fma2(acc[0][1], h0d, w.y);
            fma2(acc[1][0], h1d, w.x); fma2(acc[1][1], h1d, w.y);
            fma2(acc[2][0], h2d, w.x); fma2(acc[2][1], h2d, w.y);
            fma2(acc[3][0], h3d, w.x); fma2(acc[3][1], h3d, w.y);
        }

#pragma unroll
        for (int i = 0; i < 4; i++)
#pragma unroll
            for (int p = 0; p < 2; p++)
                red[((warp * 8) + (i * 2 + p)) * 32 + lane] = acc[i][p];
        __syncthreads();                        // sync1: partials visible

        float r0 = 0.f, r1 = 0.f;
        if (tid < 256) {
            float sx = 0.f, sy = 0.f;
#pragma unroll
            for (int w2 = 0; w2 < 16; ++w2) {
                float2 v = unpack2(red[(w2 * 8 + rq) * 32 + rl]);
                sx += v.x; sy += v.y;
            }
            r0 = tanhf(sx + pr.x);
            r1 = tanhf(sy + pr.y);
            float* rc = g_ring + (s & 1) * (1032 * 64);
            rc[rn * 64 + rb] = r0;
            rc[(rn + 1) * 64 + rb] = r1;
        }
        __syncthreads();   // sync2: ring writes done; red safe for next STS

        if (s != NS - 1) {
            if (tid == 0) {
                asm volatile("red.release.gpu.global.add.u32 [%0], %1;"
                             :: "l"(myctr), "r"(1u) : "memory");
            }
            // Overlap with other CTAs' progress: g_H writes + g_P prefetch.
            if (tid < 256) {
                *(float2*)&g_H[pb + (size_t)s * NF] =
                    make_float2(tf32r(r0), tf32r(r1));
                pr = *(const float2*)&g_P[pb + (size_t)(s + 1) * NF];
            }
        } else {
            if (tid < 256) {
                *(float2*)&g_H[pb + (size_t)s * NF] =
                    make_float2(tf32r(r0), tf32r(r1));
            }
        }
    }
}

extern "C" void kernel_launch(void* const* d_in, const int* in_sizes, int n_in,
                              void* d_out, int out_size)
{
    const float* x   = (const float*)d_in[0];
    const float* h0  = (const float*)d_in[1];
    const float* Wih = (const float*)d_in[2];
    const float* bih = (const float*)d_in[3];
    const float* Who = (const float*)d_in[4];
    const float* bho = (const float*)d_in[5];
    float* out = (float*)d_out;

    float *pP = nullptr, *pH = nullptr, *pWx = nullptr, *pWo = nullptr;
    cudaGetSymbolAddress((void**)&pP, g_P);
    cudaGetSymbolAddress((void**)&pH, g_H);
    cudaGetSymbolAddress((void**)&pWx, g_Wx);
    cudaGetSymbolAddress((void**)&pWo, g_Who);

    const int GEMM_SMEM = 4 * 128 * SST * 4;   // 73728 B
    const int SCAN_SMEM = 98304;

    static bool attr_done = false;
    if (!attr_done) {
        cudaFuncSetAttribute(rnn_scan, cudaFuncAttributeMaxDynamicSharedMemorySize, SCAN_SMEM);
        cudaFuncSetAttribute(gemm_mma, cudaFuncAttributeMaxDynamicSharedMemorySize, GEMM_SMEM);
        attr_done = true;
    }

    // user idx 0: fused init
    fused_init<<<32768, 256>>>(x, Wih, Who, h0);
    // user idx 1: x_proj = x_r @ W_x^T + b_ih -> g_P
    gemm_mma<<<dim3(8, 256), 256, GEMM_SMEM>>>(pH, pWx, bih, pP);
    // user idx 2: pad so profiler (user idx 3) hits the scan
    knop<<<1, 32>>>();
    // user idx 3: persistent recurrence scan  <-- ncu capture
    rnn_scan<<<128, 512, SCAN_SMEM>>>(Wih);
    // user idx 4: out = h_r @ W_ho^T + b_ho
    gemm_mma<<<dim3(8, 256), 256, GEMM_SMEM>>>(pH, pWo, bho, out);
}